// round 6
// baseline (speedup 1.0000x reference)
#include <cuda_runtime.h>
#include <cstdint>

// ---------------------------------------------------------------------------
// Router: r[b,e] = || W[e] @ x[b] ||_2
//   x: [8192, 4096] f32, W: [16, 64, 4096] f32 (row-major, D contiguous),
//   out: [8192, 16] f32.
// GEMM  C[8192,1024] = X @ W^T  via legacy tensor path
// mma.sync.m16n8k8.tf32 (base sm_103 target: tcgen05 is rejected by this
// build's ptxas, which targets sm_103 without the 'a' feature set).
// Operands are cvt.rna.tf32-rounded in registers -> unbiased, rel_err ~1e-4.
// Epilogue: per-row sum of squares over each 64-col expert group + sqrt.
// ---------------------------------------------------------------------------

#define BDIM   8192
#define DDIM   4096
#define EDIM   16
#define NTOT   1024                    /* E*K columns                    */
#define BM     128
#define BN     256
#define BK     32
#define STAGES 3
#define KT     (DDIM / BK)             /* 128 mainloop iterations        */
#define LDA    (BK + 4)                /* padded row stride (floats)     */
#define A_STG  (BM * LDA)              /* 4608 floats / stage            */
#define B_STG  (BN * LDA)              /* 9216 floats / stage            */
#define SMEM_BYTES (STAGES * (A_STG + B_STG) * 4)   /* 165888 B          */

__device__ __forceinline__ uint32_t f2tf32(float f) {
    uint32_t u;
    asm("cvt.rna.tf32.f32 %0, %1;" : "=r"(u) : "f"(f));
    return u;
}

__device__ __forceinline__ void mma_tf32(float c[4], const uint32_t a[4],
                                         const uint32_t b[2]) {
    asm volatile(
        "mma.sync.aligned.m16n8k8.row.col.f32.tf32.tf32.f32 "
        "{%0,%1,%2,%3}, {%4,%5,%6,%7}, {%8,%9}, {%0,%1,%2,%3};"
        : "+f"(c[0]), "+f"(c[1]), "+f"(c[2]), "+f"(c[3])
        : "r"(a[0]), "r"(a[1]), "r"(a[2]), "r"(a[3]), "r"(b[0]), "r"(b[1]));
}

__device__ __forceinline__ void cp16(uint32_t dst, const float* src) {
    asm volatile("cp.async.cg.shared.global [%0], [%1], 16;"
                 :: "r"(dst), "l"(src) : "memory");
}

// ---------------------------------------------------------------------------
// grid = (NTOT/BN = 4, BDIM/BM = 64); blockIdx.x = n-tile (fastest) so the
// 4 n-tiles of an m-tile are co-resident -> A is fetched from DRAM once.
// 256 threads = 8 warps arranged 2(m) x 4(n); warp tile 64x64 = one expert.
// ---------------------------------------------------------------------------
__global__ __launch_bounds__(256, 1)
void router_kernel(const float* __restrict__ x, const float* __restrict__ w,
                   float* __restrict__ out) {
    extern __shared__ float smem[];
    float* As = smem;                       // [STAGES][BM][LDA]
    float* Bs = smem + STAGES * A_STG;      // [STAGES][BN][LDA]

    const int tid  = threadIdx.x;
    const int lane = tid & 31;
    const int wid  = tid >> 5;
    const int wm   = wid & 1;               // 0..1  (m-warp)
    const int wn   = wid >> 1;              // 0..3  (n-warp / expert)

    const int m_base = blockIdx.y * BM;
    const int n_base = blockIdx.x * BN;

    // ---- cp.async producer mapping: thread -> (row = tid/8, 16B chunk = tid%8)
    const int lrow = tid >> 3;               // 0..31
    const int lch  = tid & 7;                // 0..7
    const float* gA = x + (size_t)(m_base + lrow) * DDIM + lch * 4;
    const float* gB = w + (size_t)(n_base + lrow) * DDIM + lch * 4;
    const uint32_t sA0 = (uint32_t)__cvta_generic_to_shared(As)
                       + (uint32_t)(lrow * LDA + lch * 4) * 4u;
    const uint32_t sB0 = (uint32_t)__cvta_generic_to_shared(Bs)
                       + (uint32_t)(lrow * LDA + lch * 4) * 4u;

    auto load_stage = [&](int s, int k0) {
        const uint32_t a = sA0 + (uint32_t)(s * A_STG) * 4u;
        const float* ga = gA + k0;
#pragma unroll
        for (int p = 0; p < BM / 32; ++p)                 // 4 passes of 32 rows
            cp16(a + (uint32_t)(p * 32 * LDA) * 4u, ga + (size_t)(p * 32) * DDIM);
        const uint32_t b = sB0 + (uint32_t)(s * B_STG) * 4u;
        const float* gb = gB + k0;
#pragma unroll
        for (int p = 0; p < BN / 32; ++p)                 // 8 passes of 32 rows
            cp16(b + (uint32_t)(p * 32 * LDA) * 4u, gb + (size_t)(p * 32) * DDIM);
    };

    // ---- prologue: fill STAGES-1 stages
#pragma unroll
    for (int s = 0; s < STAGES - 1; ++s) {
        load_stage(s, s * BK);
        asm volatile("cp.async.commit_group;" ::: "memory");
    }

    float acc[4][8][4];
#pragma unroll
    for (int mt = 0; mt < 4; ++mt)
#pragma unroll
        for (int nt = 0; nt < 8; ++nt)
#pragma unroll
            for (int i = 0; i < 4; ++i) acc[mt][nt][i] = 0.f;

    const float* Aw = As + wm * 64 * LDA;    // warp's 64 m-rows
    const float* Bw = Bs + wn * 64 * LDA;    // warp's 64 n-rows (one expert)
    const int g = lane >> 2;                 // group id (row within octet)
    const int q = lane & 3;                  // quad id (k/col within frag)

#pragma unroll 1
    for (int kt = 0; kt < KT; ++kt) {
        // stage kt is group #(kt+1); allow 1 group in flight
        asm volatile("cp.async.wait_group %0;" :: "n"(STAGES - 2) : "memory");
        __syncthreads();   // data visible to all; prev compute done -> safe overwrite

        const int pf = kt + STAGES - 1;
        if (pf < KT) load_stage(pf % STAGES, pf * BK);
        asm volatile("cp.async.commit_group;" ::: "memory");  // commit (maybe empty)

        const int cur = kt % STAGES;
        const float* Ac = Aw + cur * A_STG;
        const float* Bc = Bw + cur * B_STG;

#pragma unroll
        for (int ks = 0; ks < BK / 8; ++ks) {            // 4 k-steps of K=8
            uint32_t af[4][4], bf[8][2];
            const int c = ks * 8 + q;
#pragma unroll
            for (int mt = 0; mt < 4; ++mt) {             // conflict-free LDS
                const float* p = Ac + (mt * 16 + g) * LDA + c;
                af[mt][0] = f2tf32(p[0]);
                af[mt][1] = f2tf32(p[8 * LDA]);
                af[mt][2] = f2tf32(p[4]);
                af[mt][3] = f2tf32(p[8 * LDA + 4]);
            }
#pragma unroll
            for (int nt = 0; nt < 8; ++nt) {
                const float* p = Bc + (nt * 8 + g) * LDA + c;
                bf[nt][0] = f2tf32(p[0]);
                bf[nt][1] = f2tf32(p[4]);
            }
#pragma unroll
            for (int mt = 0; mt < 4; ++mt)
#pragma unroll
                for (int nt = 0; nt < 8; ++nt)
                    mma_tf32(acc[mt][nt], af[mt], bf[nt]);
        }
    }

    // ---- epilogue: ||.||_2 over this warp's 64 n-cols (= one expert) -------
    // C frag: c0/c1 at row g (+16*mt +64*wm), cols 2q / 2q+1 (+8*nt);
    //         c2/c3 at row g+8. Quad lanes (xor 1, xor 2) cover all 8 cols.
    const int e = blockIdx.x * (BN / 64) + wn;
#pragma unroll
    for (int mt = 0; mt < 4; ++mt) {
        float s0 = 0.f, s1 = 0.f;
#pragma unroll
        for (int nt = 0; nt < 8; ++nt) {
            s0 = fmaf(acc[mt][nt][0], acc[mt][nt][0], s0);
            s0 = fmaf(acc[mt][nt][1], acc[mt][nt][1], s0);
            s1 = fmaf(acc[mt][nt][2], acc[mt][nt][2], s1);
            s1 = fmaf(acc[mt][nt][3], acc[mt][nt][3], s1);
        }
        s0 += __shfl_xor_sync(0xffffffffu, s0, 1);
        s0 += __shfl_xor_sync(0xffffffffu, s0, 2);
        s1 += __shfl_xor_sync(0xffffffffu, s1, 1);
        s1 += __shfl_xor_sync(0xffffffffu, s1, 2);
        if (q == 0) {
            const int row = m_base + wm * 64 + mt * 16 + g;
            out[(size_t)row * EDIM + e]       = sqrtf(s0);
            out[(size_t)(row + 8) * EDIM + e] = sqrtf(s1);
        }
    }
}

// ---------------------------------------------------------------------------
extern "C" void kernel_launch(void* const* d_in, const int* in_sizes, int n_in,
                              void* d_out, int out_size) {
    (void)in_sizes; (void)n_in; (void)out_size;
    const float* x = (const float*)d_in[0];   // [8192, 4096]
    const float* w = (const float*)d_in[1];   // [16, 64, 4096] == [1024, 4096]
    float* out = (float*)d_out;               // [8192, 16]

    cudaFuncSetAttribute(router_kernel,
                         cudaFuncAttributeMaxDynamicSharedMemorySize, SMEM_BYTES);
    router_kernel<<<dim3(NTOT / BN, BDIM / BM), 256, SMEM_BYTES>>>(x, w, out);
}